// round 6
// baseline (speedup 1.0000x reference)
#include <cuda_runtime.h>
#include <cuda_bf16.h>
#include <math.h>
#include <stdint.h>

#define RR 262144   // B*N
#define NN 65536
#define HH 6

typedef unsigned long long u64;

// ============================ scratch (device globals) ============================
__device__ float g_kv[4 * HH * 32 * 32];                   // [b][h][d][e]
__device__ __nv_bfloat16 g_xh[RR * 192], g_xl[RR * 192];   // x split
__device__ __nv_bfloat16 g_qh[RR * 192], g_ql[RR * 192];   // q split [r][h*32+d]
__device__ __nv_bfloat16 g_hh[RR * 192], g_hl[RR * 192];   // h split (o1 out)
__device__ __nv_bfloat16 g_wh[960 * 192], g_wl[960 * 192]; // weights: qkv(0..575), o1(576..767), o2(768..959)

// ============================ helpers ============================
__device__ __forceinline__ uint32_t smem_u32(const void* p) {
    uint32_t a;
    asm("{ .reg .u64 t; cvta.to.shared.u64 t, %1; cvt.u32.u64 %0, t; }" : "=r"(a) : "l"(p));
    return a;
}
__device__ __forceinline__ void ldsm_x4(uint32_t a[4], uint32_t addr) {
    asm volatile("ldmatrix.sync.aligned.m8n8.x4.shared.b16 {%0,%1,%2,%3}, [%4];"
        : "=r"(a[0]), "=r"(a[1]), "=r"(a[2]), "=r"(a[3]) : "r"(addr));
}
__device__ __forceinline__ void ldsm_x2(uint32_t a[2], uint32_t addr) {
    asm volatile("ldmatrix.sync.aligned.m8n8.x2.shared.b16 {%0,%1}, [%2];"
        : "=r"(a[0]), "=r"(a[1]) : "r"(addr));
}
__device__ __forceinline__ void mma_bf16(float c[4], const uint32_t a[4], const uint32_t b[2]) {
    asm volatile(
        "mma.sync.aligned.m16n8k16.row.col.f32.bf16.bf16.f32 "
        "{%0,%1,%2,%3}, {%4,%5,%6,%7}, {%8,%9}, {%0,%1,%2,%3};"
        : "+f"(c[0]), "+f"(c[1]), "+f"(c[2]), "+f"(c[3])
        : "r"(a[0]), "r"(a[1]), "r"(a[2]), "r"(a[3]), "r"(b[0]), "r"(b[1]));
}
__device__ __forceinline__ void cpa16(uint32_t dst, const void* src) {
    asm volatile("cp.async.ca.shared.global [%0], [%1], 16;" :: "r"(dst), "l"(src));
}
__device__ __forceinline__ void cp_commit() {
    asm volatile("cp.async.commit_group;" ::: "memory");
}
template<int N> __device__ __forceinline__ void cp_wait() {
    asm volatile("cp.async.wait_group %0;" :: "n"(N) : "memory");
}
__device__ __forceinline__ float warp_sum(float v) {
    v += __shfl_xor_sync(0xffffffffu, v, 16);
    v += __shfl_xor_sync(0xffffffffu, v, 8);
    v += __shfl_xor_sync(0xffffffffu, v, 4);
    v += __shfl_xor_sync(0xffffffffu, v, 2);
    v += __shfl_xor_sync(0xffffffffu, v, 1);
    return v;
}

union BF4 { __nv_bfloat16 h[4]; u64 u; };
__device__ __forceinline__ void split4(float4 v, BF4& hi, BF4& lo) {
    float f[4] = {v.x, v.y, v.z, v.w};
#pragma unroll
    for (int j = 0; j < 4; j++) {
        __nv_bfloat16 h = __float2bfloat16(f[j]);
        hi.h[j] = h;
        lo.h[j] = __float2bfloat16(f[j] - __bfloat162float(h));
    }
}
__device__ __forceinline__ void split1(float v, __nv_bfloat16& h, __nv_bfloat16& l) {
    h = __float2bfloat16(v);
    l = __float2bfloat16(v - __bfloat162float(h));
}

// ============================ split kernels ============================
__global__ __launch_bounds__(256) void split_x_kernel(const float* __restrict__ src) {
    int stride = gridDim.x * blockDim.x;
    for (int i = blockIdx.x * blockDim.x + threadIdx.x; i < RR * 48; i += stride) {
        float4 v = ((const float4*)src)[i];
        BF4 hi, lo; split4(v, hi, lo);
        ((u64*)g_xh)[i] = hi.u;
        ((u64*)g_xl)[i] = lo.u;
    }
}
__global__ __launch_bounds__(256) void split_w_kernel(
    const float* __restrict__ qkvw, const float* __restrict__ o1w, const float* __restrict__ o2w)
{
    int stride = gridDim.x * blockDim.x;
    for (int i = blockIdx.x * blockDim.x + threadIdx.x; i < 960 * 48; i += stride) {
        float4 v;
        if (i < 27648)      v = ((const float4*)qkvw)[i];
        else if (i < 36864) v = ((const float4*)o1w)[i - 27648];
        else                v = ((const float4*)o2w)[i - 36864];
        BF4 hi, lo; split4(v, hi, lo);
        ((u64*)g_wh)[i] = hi.u;
        ((u64*)g_wl)[i] = lo.u;
    }
}
__global__ void zero_kv_kernel() {
    int i = blockIdx.x * blockDim.x + threadIdx.x;
    if (i < 4 * HH * 32 * 32) g_kv[i] = 0.f;
}

// ============================ shared GEMM pieces ============================
// smem: A_hi [128][200]b16 @0, A_lo @51200, W bufs @102400 (2 x 39936)
#define OFF_AL 51200
#define OFF_W  102400
#define WBUF   39936
#define WHALF  19968
#define SMEM_DYN 182272

__device__ __forceinline__ void load_w_chunk(uint32_t sbase, int wrow0, int n, int tid) {
    int ct = n >> 1, kc = n & 1, buf = n & 1;
    uint32_t wb = sbase + OFF_W + buf * WBUF;
    const char* bh = (const char*)g_wh;
    const char* bl = (const char*)g_wl;
    for (int i = tid; i < 96 * 12; i += 256) {
        int r = i / 12, j = i - (i / 12) * 12;
        size_t src = (size_t)(wrow0 + ct * 96 + r) * 384 + (size_t)kc * 192 + (size_t)j * 16;
        uint32_t dst = wb + r * 208 + j * 16;
        cpa16(dst, bh + src);
        cpa16(dst + WHALF, bl + src);
    }
}

// Main-loop body macro: 2 k-chunks for column tile ct, W double-buffered.
#define MMA_COLTILE(ct, NCH, wrow0)                                                        \
    _Pragma("unroll")                                                                      \
    for (int kc = 0; kc < 2; kc++) {                                                       \
        int n = (ct) * 2 + kc;                                                             \
        if (n + 1 < (NCH)) { load_w_chunk(sbase, (wrow0), n + 1, tid); cp_commit(); cp_wait<1>(); } \
        else cp_wait<0>();                                                                 \
        __syncthreads();                                                                   \
        uint32_t wb = sbase + OFF_W + (n & 1) * WBUF;                                      \
        _Pragma("unroll")                                                                  \
        for (int ksl = 0; ksl < 6; ksl++) {                                                \
            int ks = kc * 6 + ksl;                                                         \
            uint32_t ahi[4][4], alo[4][4], bhi[3][2], blo[3][2];                           \
            uint32_t aoff = sbase + (uint32_t)(rowA * 400 + (ks * 16 + kofsA) * 2);        \
            _Pragma("unroll")                                                              \
            for (int mt = 0; mt < 4; mt++) {                                               \
                ldsm_x4(ahi[mt], aoff + mt * (16 * 400));                                  \
                ldsm_x4(alo[mt], OFF_AL + aoff + mt * (16 * 400));                         \
            }                                                                              \
            uint32_t boff = wb + (uint32_t)(rowB * 208 + (ksl * 16 + kofsB) * 2);          \
            _Pragma("unroll")                                                              \
            for (int nt = 0; nt < 3; nt++) {                                               \
                ldsm_x2(bhi[nt], boff + nt * (8 * 208));                                   \
                ldsm_x2(blo[nt], boff + WHALF + nt * (8 * 208));                           \
            }                                                                              \
            _Pragma("unroll")                                                              \
            for (int mt = 0; mt < 4; mt++)                                                 \
                _Pragma("unroll")                                                          \
                for (int nt = 0; nt < 3; nt++)                                             \
                    mma_bf16(acc[mt][nt], ahi[mt], bhi[nt]);                               \
            _Pragma("unroll")                                                              \
            for (int mt = 0; mt < 4; mt++)                                                 \
                _Pragma("unroll")                                                          \
                for (int nt = 0; nt < 3; nt++)                                             \
                    mma_bf16(acc[mt][nt], alo[mt], bhi[nt]);                               \
            _Pragma("unroll")                                                              \
            for (int mt = 0; mt < 4; mt++)                                                 \
                _Pragma("unroll")                                                          \
                for (int nt = 0; nt < 3; nt++)                                             \
                    mma_bf16(acc[mt][nt], ahi[mt], blo[nt]);                               \
        }                                                                                  \
        __syncthreads();                                                                   \
    }

// ============================ QKV GEMM + fused LN/kv ============================
// Per CTA: 128 rows, 6 col tiles (= 6 heads). Epilogue: q -> split bf16 out;
// k,v -> smem stage -> LN(ddof=1) -> kv outer-product partial -> atomicAdd.
__global__ __launch_bounds__(256) void gemm_qkv(
    const float* __restrict__ bias,
    const float* __restrict__ klnw, const float* __restrict__ klnb,
    const float* __restrict__ vlnw, const float* __restrict__ vlnb)
{
    extern __shared__ char sm[];
    uint32_t sbase = smem_u32(sm);
    int tid = threadIdx.x;
    size_t row0 = (size_t)blockIdx.x * 128;
    int b = (int)(row0 / NN);

    {
        const char* ah = (const char*)g_xh;
        const char* al = (const char*)g_xl;
        for (int i = tid; i < 128 * 24; i += 256) {
            int r = i / 24, j = i - (i / 24) * 24;
            size_t src = (row0 + r) * 384 + (size_t)j * 16;
            uint32_t dst = (uint32_t)(r * 400 + j * 16);
            cpa16(sbase + dst, ah + src);
            cpa16(sbase + OFF_AL + dst, al + src);
        }
    }
    load_w_chunk(sbase, 0, 0, tid);
    cp_commit();

    int l = tid & 31, wid = tid >> 5;
    int warp_m = wid >> 2, warp_n = wid & 3;
    int rowA = warp_m * 64 + (l & 7) + ((l >> 3) & 1) * 8;
    int kofsA = (l >> 4) * 8;
    int rowB = warp_n * 24 + (l & 7);
    int kofsB = ((l >> 3) & 1) * 8;

    float* stage = (float*)(sm + OFF_W + WBUF);   // buf1 region, safe during epilogue

#pragma unroll 1
    for (int ct = 0; ct < 6; ct++) {
        float acc[4][3][4];
#pragma unroll
        for (int mt = 0; mt < 4; mt++)
#pragma unroll
            for (int nt = 0; nt < 3; nt++)
#pragma unroll
                for (int j = 0; j < 4; j++) acc[mt][nt][j] = 0.f;

        MMA_COLTILE(ct, 12, 0)

        // ---- epilogue: q out, k/v stage ----
        int h = ct;
#pragma unroll
        for (int mt = 0; mt < 4; mt++) {
#pragma unroll
            for (int nt = 0; nt < 3; nt++) {
                int lcol = warp_n * 24 + nt * 8 + 2 * (l & 3);
                float b0 = bias[h * 96 + lcol], b1 = bias[h * 96 + lcol + 1];
                int rl0 = warp_m * 64 + mt * 16 + (l >> 2);
#pragma unroll
                for (int half = 0; half < 2; half++) {
                    int rl = rl0 + half * 8;
                    float v0 = acc[mt][nt][half * 2 + 0] + b0;
                    float v1 = acc[mt][nt][half * 2 + 1] + b1;
                    if (lcol < 32) {
                        size_t r = row0 + rl;
                        __nv_bfloat162 ph, pl;
                        split1(v0, ph.x, pl.x);
                        split1(v1, ph.y, pl.y);
                        *(__nv_bfloat162*)&g_qh[r * 192 + h * 32 + lcol] = ph;
                        *(__nv_bfloat162*)&g_ql[r * 192 + h * 32 + lcol] = pl;
                    } else {
                        float2 p; p.x = v0; p.y = v1;
                        *(float2*)&stage[rl * 68 + (lcol - 32)] = p;
                    }
                }
            }
        }
        __syncthreads();

        // ---- LN(k), LN(v), kv outer product ----
        {
            float kw = klnw[h * 32 + l], kb = klnb[h * 32 + l];
            float vw = vlnw[h * 32 + l], vb = vlnb[h * 32 + l];
            float accd[32];
#pragma unroll
            for (int d = 0; d < 32; d++) accd[d] = 0.f;

            for (int r16 = 0; r16 < 16; r16++) {
                int row = wid * 16 + r16;
                float kx = stage[row * 68 + l];
                float vx = stage[row * 68 + 32 + l];

                float km = warp_sum(kx) * (1.0f / 32.0f);
                float kt = kx - km;
                float ks = sqrtf(warp_sum(kt * kt) * (1.0f / 31.0f));
                float lnk = kw * (kt / (ks + 1e-5f)) + kb;

                float vm = warp_sum(vx) * (1.0f / 32.0f);
                float vt = vx - vm;
                float vs = sqrtf(warp_sum(vt * vt) * (1.0f / 31.0f));
                float lnv = vw * (vt / (vs + 1e-5f)) + vb;

#pragma unroll
                for (int d = 0; d < 32; d++)
                    accd[d] = fmaf(__shfl_sync(0xffffffffu, lnk, d), lnv, accd[d]);
            }
            __syncthreads();
#pragma unroll
            for (int d = 0; d < 32; d++) stage[(wid * 32 + d) * 32 + l] = accd[d];
            __syncthreads();
            int bh = b * 6 + h;
            for (int i = tid; i < 1024; i += 256) {
                float s = 0.f;
#pragma unroll
                for (int w8 = 0; w8 < 8; w8++) s += stage[(w8 * 32 + (i >> 5)) * 32 + (i & 31)];
                atomicAdd(&g_kv[bh * 1024 + i], s * (1.0f / 65536.0f));
            }
            __syncthreads();
        }
    }
}

// ============================ o1 (fused attn) / o2 GEMM ============================
// FUSED=1: A-phase computes ret = q@kv + x (3-pass bf16 HMMA per head, warp-private
//          16-row tiles), written in place into the A smem region.
// EPI: 1 = gelu -> g_hh/g_hl split, 2 = +resid -> fp32 Oext
template<int EPI, int FUSED>
__global__ __launch_bounds__(256) void gemm_mlp(
    int wrow0, const float* __restrict__ bias,
    float* __restrict__ Oext, const float* __restrict__ x, int ncols)
{
    extern __shared__ char sm[];
    uint32_t sbase = smem_u32(sm);
    int tid = threadIdx.x;
    size_t row0 = (size_t)blockIdx.x * 128;
    int l = tid & 31, wid = tid >> 5;

    if (FUSED) {
        // q split -> A region
        const char* ah = (const char*)g_qh;
        const char* al = (const char*)g_ql;
        for (int i = tid; i < 128 * 24; i += 256) {
            int r = i / 24, j = i - (i / 24) * 24;
            size_t src = (row0 + r) * 384 + (size_t)j * 16;
            uint32_t dst = (uint32_t)(r * 400 + j * 16);
            cpa16(sbase + dst, ah + src);
            cpa16(sbase + OFF_AL + dst, al + src);
        }
        cp_commit();

        // kv^T split in W region: [h][e][40 halves] pitch 80B
        __nv_bfloat16* kvh_s = (__nv_bfloat16*)(sm + OFF_W);
        __nv_bfloat16* kvl_s = (__nv_bfloat16*)(sm + OFF_W + 15360);
        int b = (int)(row0 / NN);
        for (int i = tid; i < 6144; i += 256) {
            int h = i >> 10, d = (i >> 5) & 31, e = i & 31;
            float v = g_kv[(b * 6 + h) * 1024 + d * 32 + e];
            __nv_bfloat16 hi, lo; split1(v, hi, lo);
            kvh_s[(h * 32 + e) * 40 + d] = hi;
            kvl_s[(h * 32 + e) * 40 + d] = lo;
        }
        cp_wait<0>();
        __syncthreads();

        // mini GEMMs: warp owns rows wid*16..+15; per head: C[16x32] = q[16x32] @ kv
        int mrow = wid * 16;
        uint32_t arow = (uint32_t)((mrow + (l & 7) + ((l >> 3) & 1) * 8) * 400);
        uint32_t kA = (uint32_t)((l >> 4) * 8);
        uint32_t kvb = sbase + (uint32_t)OFF_W;
#pragma unroll 1
        for (int h = 0; h < 6; h++) {
            uint32_t qh_f[2][4], ql_f[2][4];
#pragma unroll
            for (int kc = 0; kc < 2; kc++) {
                uint32_t ao = arow + (uint32_t)((h * 32 + kc * 16 + kA) * 2);
                ldsm_x4(qh_f[kc], sbase + ao);
                ldsm_x4(ql_f[kc], sbase + OFF_AL + ao);
            }
            float accm[4][4];
#pragma unroll
            for (int nt = 0; nt < 4; nt++)
#pragma unroll
                for (int j = 0; j < 4; j++) accm[nt][j] = 0.f;
#pragma unroll
            for (int nt = 0; nt < 4; nt++) {
                uint32_t bo = (uint32_t)((h * 32 + nt * 8 + (l & 7)) * 80 + ((l >> 3) & 1) * 16);
#pragma unroll
                for (int kc = 0; kc < 2; kc++) {
                    uint32_t bh_f[2], bl_f[2];
                    ldsm_x2(bh_f, kvb + bo + kc * 32);
                    ldsm_x2(bl_f, kvb + 15360 + bo + kc * 32);
                    mma_bf16(accm[nt], qh_f[kc], bh_f);
                    mma_bf16(accm[nt], ql_f[kc], bh_f);
                    mma_bf16(accm[nt], qh_f[kc], bl_f);
                }
            }
            // ret = acc + x, overwrite A region (own rows/cols only)
#pragma unroll
            for (int nt = 0; nt < 4; nt++) {
                int col = h * 32 + nt * 8 + 2 * (l & 3);
#pragma unroll
                for (int half = 0; half < 2; half++) {
                    int rl = mrow + (l >> 2) + half * 8;
                    size_t r = row0 + rl;
                    float2 xv = *(const float2*)&x[r * 192 + col];
                    float v0 = accm[nt][half * 2 + 0] + xv.x;
                    float v1 = accm[nt][half * 2 + 1] + xv.y;
                    __nv_bfloat162 ph, pl;
                    split1(v0, ph.x, pl.x);
                    split1(v1, ph.y, pl.y);
                    *(__nv_bfloat162*)(sm + rl * 400 + col * 2) = ph;
                    *(__nv_bfloat162*)(sm + OFF_AL + rl * 400 + col * 2) = pl;
                }
            }
        }
        __syncthreads();
    } else {
        const char* ah = (const char*)g_hh;
        const char* al = (const char*)g_hl;
        for (int i = tid; i < 128 * 24; i += 256) {
            int r = i / 24, j = i - (i / 24) * 24;
            size_t src = (row0 + r) * 384 + (size_t)j * 16;
            uint32_t dst = (uint32_t)(r * 400 + j * 16);
            cpa16(sbase + dst, ah + src);
            cpa16(sbase + OFF_AL + dst, al + src);
        }
        cp_commit();
    }

    load_w_chunk(sbase, wrow0, 0, tid);
    cp_commit();

    int warp_m = wid >> 2, warp_n = wid & 3;
    int rowA = warp_m * 64 + (l & 7) + ((l >> 3) & 1) * 8;
    int kofsA = (l >> 4) * 8;
    int rowB = warp_n * 24 + (l & 7);
    int kofsB = ((l >> 3) & 1) * 8;

#pragma unroll 1
    for (int ct = 0; ct < 2; ct++) {
        float acc[4][3][4];
#pragma unroll
        for (int mt = 0; mt < 4; mt++)
#pragma unroll
            for (int nt = 0; nt < 3; nt++)
#pragma unroll
                for (int j = 0; j < 4; j++) acc[mt][nt][j] = 0.f;

        MMA_COLTILE(ct, 4, wrow0)

#pragma unroll
        for (int mt = 0; mt < 4; mt++) {
#pragma unroll
            for (int nt = 0; nt < 3; nt++) {
                int col = ct * 96 + warp_n * 24 + nt * 8 + 2 * (l & 3);
                float b0 = bias[col], b1 = bias[col + 1];
                size_t rg = row0 + warp_m * 64 + mt * 16 + (l >> 2);
#pragma unroll
                for (int half = 0; half < 2; half++) {
                    size_t r = rg + half * 8;
                    float v0 = acc[mt][nt][half * 2 + 0] + b0;
                    float v1 = acc[mt][nt][half * 2 + 1] + b1;
                    if (EPI == 1) {
                        v0 = 0.5f * v0 * (1.0f + erff(v0 * 0.70710678118654752440f));
                        v1 = 0.5f * v1 * (1.0f + erff(v1 * 0.70710678118654752440f));
                        __nv_bfloat162 ph, pl;
                        split1(v0, ph.x, pl.x);
                        split1(v1, ph.y, pl.y);
                        *(__nv_bfloat162*)&g_hh[r * 192 + col] = ph;
                        *(__nv_bfloat162*)&g_hl[r * 192 + col] = pl;
                    } else {
                        v0 += x[r * (size_t)ncols + col];
                        v1 += x[r * (size_t)ncols + col + 1];
                        float2 p; p.x = v0; p.y = v1;
                        *(float2*)&Oext[r * (size_t)ncols + col] = p;
                    }
                }
            }
        }
    }
}

extern "C" void kernel_launch(void* const* d_in, const int* in_sizes, int n_in,
                              void* d_out, int out_size)
{
    const float* x     = (const float*)d_in[0];
    const float* qkv_w = (const float*)d_in[1];
    const float* qkv_b = (const float*)d_in[2];
    const float* o1_w  = (const float*)d_in[3];
    const float* o1_b  = (const float*)d_in[4];
    const float* o2_w  = (const float*)d_in[5];
    const float* o2_b  = (const float*)d_in[6];
    const float* klnw  = (const float*)d_in[7];
    const float* klnb  = (const float*)d_in[8];
    const float* vlnw  = (const float*)d_in[9];
    const float* vlnb  = (const float*)d_in[10];
    float* out = (float*)d_out;

    cudaFuncSetAttribute(gemm_qkv, cudaFuncAttributeMaxDynamicSharedMemorySize, SMEM_DYN);
    cudaFuncSetAttribute(gemm_mlp<1, 1>, cudaFuncAttributeMaxDynamicSharedMemorySize, SMEM_DYN);
    cudaFuncSetAttribute(gemm_mlp<2, 0>, cudaFuncAttributeMaxDynamicSharedMemorySize, SMEM_DYN);

    split_x_kernel<<<8192, 256>>>(x);
    split_w_kernel<<<180, 256>>>(qkv_w, o1_w, o2_w);
    zero_kv_kernel<<<24, 1024>>>();

    // QKV + LN + kv reduction (writes q split + g_kv)
    gemm_qkv<<<RR / 128, 256, SMEM_DYN>>>(qkv_b, klnw, klnb, vlnw, vlnb);
    // o1 with fused attn: ret = q@kv + x, then h = gelu(ret @ o1_w^T + b) -> split
    gemm_mlp<1, 1><<<RR / 128, 256, SMEM_DYN>>>(576, o1_b, nullptr, x, 192);
    // o2: out = h @ o2_w^T + b + x
    gemm_mlp<2, 0><<<RR / 128, 256, SMEM_DYN>>>(768, o2_b, out, x, 192);
}